// round 16
// baseline (speedup 1.0000x reference)
#include <cuda_runtime.h>
#include <cuda_fp16.h>

#define NN    100000
#define EDGES 3200000
#define INC   128
#define HID   16
#define OUTC  64
#define NBLK  ((NN + 1023) / 1024)   // 98

// Scratch (allocation-free rule: __device__ globals)
__device__ __align__(16) int    g_deg_i[NN];
__device__ __align__(16) float  g_dinv[NN];
__device__ __align__(16) int    g_off[NN + 1];
__device__ __align__(16) int    g_cur[NN];
__device__ __align__(16) int    g_srcI[EDGES];     // CSR: src index only (4B)
__device__ __align__(16) int    g_bsum[NBLK];
__device__ __align__(16) __half g_h[NN * HID];     // h1 * dinv, fp16 (32B/row)
__device__ __align__(16) __half g_h2[NN * HID];    // relu(agg1+b1) * dinv, fp16
__device__ __align__(16) float  g_agg[NN * HID];   // agg2 (fp32 for gemm2)

__global__ void k_init_deg() {
    int i = blockIdx.x * blockDim.x + threadIdx.x;
    if (i < NN) g_deg_i[i] = 1;  // self loop contributes 1
}

__global__ void k_count(const int* __restrict__ col, int E) {
    int i = blockIdx.x * blockDim.x + threadIdx.x;
    int e0 = i * 4;
    if (e0 + 3 < E) {
        int4 c4 = ((const int4*)col)[i];
        atomicAdd(&g_deg_i[c4.x], 1);
        atomicAdd(&g_deg_i[c4.y], 1);
        atomicAdd(&g_deg_i[c4.z], 1);
        atomicAdd(&g_deg_i[c4.w], 1);
    } else {
        for (int e = e0; e < E; e++) atomicAdd(&g_deg_i[col[e]], 1);
    }
}

// dinv + per-block degree sum fused (both are one pass over g_deg_i).
__global__ void k_dinv_blocksum() {
    __shared__ int sh[1024];
    int t = threadIdx.x;
    int i = blockIdx.x * 1024 + t;
    int d = (i < NN) ? g_deg_i[i] : 1;
    if (i < NN) g_dinv[i] = rsqrtf((float)d);
    sh[t] = (i < NN) ? d - 1 : 0;
    __syncthreads();
    for (int o = 512; o > 0; o >>= 1) {
        if (t < o) sh[t] += sh[t + o];
        __syncthreads();
    }
    if (t == 0) g_bsum[blockIdx.x] = sh[0];
}

// Block-level scan with inlined cross-block prefix (bscan folded in).
__global__ void k_off() {
    __shared__ int sh[1024];
    int t = threadIdx.x;
    // Phase A: this block's exclusive prefix over g_bsum
    sh[t] = (t < NBLK && t < blockIdx.x) ? g_bsum[t] : 0;
    __syncthreads();
    for (int o = 512; o > 0; o >>= 1) {
        if (t < o) sh[t] += sh[t + o];
        __syncthreads();
    }
    int boff = sh[0];
    __syncthreads();
    // Phase B: intra-block inclusive Hillis-Steele over (deg-1)
    int i = blockIdx.x * 1024 + t;
    int v = (i < NN) ? g_deg_i[i] - 1 : 0;
    sh[t] = v;
    __syncthreads();
    for (int o = 1; o < 1024; o <<= 1) {
        int u = (t >= o) ? sh[t - o] : 0;
        __syncthreads();
        sh[t] += u;
        __syncthreads();
    }
    int excl = sh[t] - v + boff;
    if (i < NN) {
        g_off[i] = excl;
        g_cur[i] = excl;
        if (i == NN - 1) g_off[NN] = excl + v;
    }
}

__global__ void k_scatter(const int* __restrict__ row,
                          const int* __restrict__ col, int E) {
    int e = blockIdx.x * blockDim.x + threadIdx.x;
    if (e >= E) return;
    int p = atomicAdd(&g_cur[col[e]], 1);
    g_srcI[p] = row[e];
}

// h' = (X @ W1) * dinv[node], stored fp16. 16 rows / 256-thread block.
__global__ void k_gemm1(const float* __restrict__ x, const float* __restrict__ W1) {
    __shared__ float4 xs[16 * 32];    // 16 rows x 32 float4 (K=128)
    __shared__ float4 wsT[16 * 33];   // 16 cols x 32 float4, stride 33 (pad)
    int r0 = blockIdx.x * 16;
    int t = threadIdx.x;
    const float4* xg = (const float4*)x;
    for (int i = t; i < 512; i += 256)
        xs[i] = xg[r0 * 32 + i];
    for (int i = t; i < 512; i += 256) {
        int c = i >> 5, k4 = i & 31;
        float4 w;
        w.x = W1[(k4 * 4 + 0) * 16 + c];
        w.y = W1[(k4 * 4 + 1) * 16 + c];
        w.z = W1[(k4 * 4 + 2) * 16 + c];
        w.w = W1[(k4 * 4 + 3) * 16 + c];
        wsT[c * 33 + k4] = w;
    }
    __syncthreads();
    int r = t >> 4, c = t & 15;
    float acc = 0.0f;
#pragma unroll
    for (int k4 = 0; k4 < 32; k4++) {
        float4 xv = xs[r * 32 + k4];
        float4 wv = wsT[c * 33 + k4];
        acc = fmaf(xv.x, wv.x, acc);
        acc = fmaf(xv.y, wv.y, acc);
        acc = fmaf(xv.z, wv.z, acc);
        acc = fmaf(xv.w, wv.w, acc);
    }
    g_h[(r0 + r) * HID + c] = __float2half(acc * g_dinv[r0 + r]);
}

__device__ __forceinline__ void acc_add8(float* a, uint4 u) {
    half2* h = (half2*)&u;
#pragma unroll
    for (int i = 0; i < 4; i++) {
        float2 f = __half22float2(h[i]);
        a[2 * i] += f.x;
        a[2 * i + 1] += f.y;
    }
}

// Warp-per-node pull over fp16 rows (32B). Lane = sub*2 + j:
// j in {0,1} covers 16B (8 cols); sub enumerates 16 edges/iter, 2x unroll.
// RELU=true: dst is __half* (g_h2), out = relu(din*acc + b1)*din.
// RELU=false: dst is float* (g_agg), out = din*acc.
template <bool RELU>
__global__ void __launch_bounds__(256) k_pullh(const __half* __restrict__ Hp,
                                               void* __restrict__ dst,
                                               const float* __restrict__ b1) {
    int n = (blockIdx.x * blockDim.x + threadIdx.x) >> 5;
    if (n >= NN) return;
    int lane = threadIdx.x & 31;
    int sub = lane >> 1, j = lane & 1;
    float din = g_dinv[n];
    const uint4* H4 = (const uint4*)Hp;  // 16B chunks; row s = chunks [2s, 2s+1]
    float a[8];
#pragma unroll
    for (int i = 0; i < 8; i++) a[i] = 0.0f;
    if (sub == 0) acc_add8(a, H4[n * 2 + j]);  // self loop
    int e = g_off[n] + sub;
    int eend = g_off[n + 1];
    for (; e + 16 < eend; e += 32) {
        int s0 = g_srcI[e], s1 = g_srcI[e + 16];
        uint4 u0 = H4[s0 * 2 + j];
        uint4 u1 = H4[s1 * 2 + j];
        acc_add8(a, u0);
        acc_add8(a, u1);
    }
    for (; e < eend; e += 16) {
        uint4 u = H4[g_srcI[e] * 2 + j];
        acc_add8(a, u);
    }
    // butterfly over sub bits (lane bits 1..4); j (bit 0) stays separate
#pragma unroll
    for (int o = 2; o < 32; o <<= 1) {
#pragma unroll
        for (int i = 0; i < 8; i++)
            a[i] += __shfl_xor_sync(0xffffffffu, a[i], o);
    }
    if (sub == 0) {
        if (RELU) {
            const float4* B = (const float4*)b1;
            float4 bA = B[2 * j], bB = B[2 * j + 1];
            float r0 = fmaxf(din * a[0] + bA.x, 0.f) * din;
            float r1 = fmaxf(din * a[1] + bA.y, 0.f) * din;
            float r2 = fmaxf(din * a[2] + bA.z, 0.f) * din;
            float r3 = fmaxf(din * a[3] + bA.w, 0.f) * din;
            float r4 = fmaxf(din * a[4] + bB.x, 0.f) * din;
            float r5 = fmaxf(din * a[5] + bB.y, 0.f) * din;
            float r6 = fmaxf(din * a[6] + bB.z, 0.f) * din;
            float r7 = fmaxf(din * a[7] + bB.w, 0.f) * din;
            uint4 o4;
            half2* oh = (half2*)&o4;
            oh[0] = __floats2half2_rn(r0, r1);
            oh[1] = __floats2half2_rn(r2, r3);
            oh[2] = __floats2half2_rn(r4, r5);
            oh[3] = __floats2half2_rn(r6, r7);
            ((uint4*)dst)[n * 2 + j] = o4;
        } else {
            float4 f0, f1;
            f0.x = din * a[0]; f0.y = din * a[1]; f0.z = din * a[2]; f0.w = din * a[3];
            f1.x = din * a[4]; f1.y = din * a[5]; f1.z = din * a[6]; f1.w = din * a[7];
            ((float4*)dst)[n * 4 + j * 2 + 0] = f0;
            ((float4*)dst)[n * 4 + j * 2 + 1] = f1;
        }
    }
}

// out = g_agg @ W2 + b2. 4 rows per 256-thread block.
__global__ void k_gemm2(const float* __restrict__ W2, const float* __restrict__ b2,
                        float* __restrict__ out) {
    __shared__ float as[4 * 16];
    __shared__ float ws[16 * 64];
    int r0 = blockIdx.x * 4;
    int t = threadIdx.x;
    if (t < 64) as[t] = g_agg[r0 * HID + t];
    for (int i = t; i < 16 * 64; i += 256) ws[i] = W2[i];
    __syncthreads();
    int r = t >> 6, c = t & 63;
    float acc = b2[c];
#pragma unroll
    for (int k = 0; k < 16; k++)
        acc = fmaf(as[r * 16 + k], ws[k * 64 + c], acc);
    out[(r0 + r) * OUTC + c] = acc;
}

extern "C" void kernel_launch(void* const* d_in, const int* in_sizes, int n_in,
                              void* d_out, int out_size) {
    const float* x   = (const float*)d_in[0];
    const int*   ei  = (const int*)d_in[1];   // JAX silently downcast int64->int32
    const float* W1  = (const float*)d_in[2];
    const float* b1  = (const float*)d_in[3];
    const float* W2  = (const float*)d_in[4];
    const float* b2  = (const float*)d_in[5];
    float*       out = (float*)d_out;

    int E = in_sizes[1] / 2;
    const int* row = ei;       // sources
    const int* col = ei + E;   // targets

    __half* p_h;   cudaGetSymbolAddress((void**)&p_h,   g_h);
    __half* p_h2;  cudaGetSymbolAddress((void**)&p_h2,  g_h2);
    float*  p_agg; cudaGetSymbolAddress((void**)&p_agg, g_agg);

    k_init_deg<<<(NN + 255) / 256, 256>>>();
    k_count<<<(E / 4 + 255) / 256, 256>>>(col, E);
    k_dinv_blocksum<<<NBLK, 1024>>>();
    k_off<<<NBLK, 1024>>>();
    k_scatter<<<(E + 255) / 256, 256>>>(row, col, E);
    k_gemm1<<<NN / 16, 256>>>(x, W1);
    k_pullh<true><<<(NN * 32 + 255) / 256, 256>>>(p_h, p_h2, b1);
    k_pullh<false><<<(NN * 32 + 255) / 256, 256>>>(p_h2, p_agg, b1);
    k_gemm2<<<NN / 4, 256>>>(W2, b2, out);
}